// round 3
// baseline (speedup 1.0000x reference)
#include <cuda_runtime.h>

#define NUM_ENTITIES 200000
#define NEG_INF -9e15f
#define ALPHA 0.2f
#define DDIM 64
#define MNB 16
#define NREL 51

// Precomputed per-relation projections (device scratch; no allocation).
__device__ float g_u1[NREL * DDIM];   // u1[r][k] = sum_d fc_W[k,d]     * rel[r,d]
__device__ float g_u2[NREL * DDIM];   // u2[r][k] = sum_d fc_W[k+64,d]  * rel[r,d]
__device__ float g_c[NREL];           // c[r]     = sum_d fc_b[d]       * rel[r,d]

// 51 blocks x 64 threads: thread k of block r computes u1[r][k], u2[r][k].
__global__ void precompute_kernel(const float* __restrict__ fc_W,
                                  const float* __restrict__ fc_b,
                                  const float* __restrict__ rel_table) {
    __shared__ float rel[DDIM];
    const int r = blockIdx.x;
    const int k = threadIdx.x;

    const float rv_k = rel_table[r * DDIM + k];
    rel[k] = rv_k;
    __syncthreads();

    float s1 = 0.f, s2 = 0.f;
#pragma unroll 8
    for (int d = 0; d < DDIM; d++) {
        float rv = rel[d];
        s1 = fmaf(fc_W[k * DDIM + d], rv, s1);
        s2 = fmaf(fc_W[(k + DDIM) * DDIM + d], rv, s2);
    }
    g_u1[r * DDIM + k] = s1;
    g_u2[r * DDIM + k] = s2;

    // c[r] = dot(fc_b, rel[r]) via per-warp shfl reduce + cross-warp combine.
    float bp = fc_b[k] * rv_k;
    bp += __shfl_xor_sync(0xffffffffu, bp, 16);
    bp += __shfl_xor_sync(0xffffffffu, bp, 8);
    bp += __shfl_xor_sync(0xffffffffu, bp, 4);
    bp += __shfl_xor_sync(0xffffffffu, bp, 2);
    bp += __shfl_xor_sync(0xffffffffu, bp, 1);
    __shared__ float warp_sum[2];
    if ((k & 31) == 0) warp_sum[k >> 5] = bp;
    __syncthreads();
    if (k == 0) g_c[r] = warp_sum[0] + warp_sum[1];
}

// One warp per item row. Lane owns dims [2*lane, 2*lane+1].
// Phase 1 issues all gathers back-to-back (MLP~16+) before any serialized
// shfl-reduction chain; phase 2 reduces all 16 logits with cross-m ILP.
__global__ void __launch_bounds__(256)
gat_kernel(const int* __restrict__ item_ids,
           const int* __restrict__ item_entities,
           const int* __restrict__ item_relations,
           const float* __restrict__ item_table,
           const float* __restrict__ entity_table,
           float* __restrict__ out,
           int N) {
    const int warp = (int)((blockIdx.x * blockDim.x + threadIdx.x) >> 5);
    const int lane = threadIdx.x & 31;
    if (warp >= N) return;

    const int iid = __ldg(item_ids + warp);
    const float2 it = *(const float2*)(item_table + iid * DDIM + 2 * lane);

    // Lanes 0..15 hold the 16 neighbor (entity, relation) ids; shfl-broadcast.
    int my_eid = 0, my_rid = 0;
    if (lane < MNB) {
        my_eid = __ldg(item_entities + warp * MNB + lane);
        my_rid = __ldg(item_relations + warp * MNB + lane);
    }
    int eid[MNB], rid[MNB];
#pragma unroll
    for (int m = 0; m < MNB; m++) {
        eid[m] = __shfl_sync(0xffffffffu, my_eid, m);
        rid[m] = __shfl_sync(0xffffffffu, my_rid, m);
    }

    // ---- Phase 1: all gathers + per-lane partial dot products ----
    float2 ent[MNB];
    float  pl[MNB];
#pragma unroll
    for (int m = 0; m < MNB; m++)
        ent[m] = *(const float2*)(entity_table + eid[m] * DDIM + 2 * lane);
#pragma unroll
    for (int m = 0; m < MNB; m++) {
        const float2 u1 = *(const float2*)(g_u1 + rid[m] * DDIM + 2 * lane);
        const float2 u2 = *(const float2*)(g_u2 + rid[m] * DDIM + 2 * lane);
        pl[m] = it.x * u1.x + it.y * u1.y + ent[m].x * u2.x + ent[m].y * u2.y;
    }

    // ---- Phase 2: 16 independent warp reductions (ILP across m per stage) ----
#pragma unroll
    for (int st = 16; st >= 1; st >>= 1) {
#pragma unroll
        for (int m = 0; m < MNB; m++)
            pl[m] += __shfl_xor_sync(0xffffffffu, pl[m], st);
    }

    float elog[MNB];
#pragma unroll
    for (int m = 0; m < MNB; m++) {
        float e = pl[m] + __ldg(g_c + rid[m]);
        e = (e > 0.f) ? e : ALPHA * e;                        // leaky_relu
        elog[m] = (eid[m] != NUM_ENTITIES) ? e : NEG_INF;     // padding mask
    }

    // Softmax over 16 logits (every lane redundantly; matches jax.nn.softmax,
    // including the all-masked -> uniform 1/16 case).
    float mx = elog[0];
#pragma unroll
    for (int m = 1; m < MNB; m++) mx = fmaxf(mx, elog[m]);
    float s = 0.f;
#pragma unroll
    for (int m = 0; m < MNB; m++) { elog[m] = __expf(elog[m] - mx); s += elog[m]; }
    const float inv = 1.f / s;

    float2 acc = it;  // + item_embs residual
#pragma unroll
    for (int m = 0; m < MNB; m++) {
        const float wm = elog[m] * inv;
        acc.x = fmaf(wm, ent[m].x, acc.x);
        acc.y = fmaf(wm, ent[m].y, acc.y);
    }
    *(float2*)(out + warp * DDIM + 2 * lane) = acc;
}

extern "C" void kernel_launch(void* const* d_in, const int* in_sizes, int n_in,
                              void* d_out, int out_size) {
    const int*   item_ids       = (const int*)d_in[0];
    const int*   item_entities  = (const int*)d_in[1];
    const int*   item_relations = (const int*)d_in[2];
    const float* item_table     = (const float*)d_in[3];
    const float* entity_table   = (const float*)d_in[4];
    const float* relation_table = (const float*)d_in[5];
    const float* fc_W           = (const float*)d_in[6];
    const float* fc_b           = (const float*)d_in[7];
    float* out = (float*)d_out;

    const int N = in_sizes[0];

    precompute_kernel<<<NREL, DDIM>>>(fc_W, fc_b, relation_table);

    // One warp per row: 8 rows per 256-thread block.
    const int blocks = (N + 7) / 8;
    gat_kernel<<<blocks, 256>>>(item_ids, item_entities, item_relations,
                                item_table, entity_table, out, N);
}

// round 4
// speedup vs baseline: 1.5036x; 1.5036x over previous
#include <cuda_runtime.h>

#define NUM_ENTITIES 200000
#define NEG_INF -9e15f
#define ALPHA 0.2f
#define DDIM 64
#define MNB 16
#define NREL 51
#define FULLMASK 0xffffffffu

// Fused per-relation projection table, lane-interleaved:
// g_u[r*256 + l*4 + {0,1,2,3}] = { u1[2l], u1[2l+1], u2[2l], u2[2l+1] }
// where u1[k] = sum_d fc_W[k,d]*rel[r,d], u2[k] = sum_d fc_W[k+64,d]*rel[r,d].
__device__ float g_u[NREL * 4 * DDIM];
__device__ float g_c[NREL];           // c[r] = dot(fc_b, rel[r])

// 51 blocks x 64 threads: thread k computes u1[k], u2[k] for relation r.
__global__ void precompute_kernel(const float* __restrict__ fc_W,
                                  const float* __restrict__ fc_b,
                                  const float* __restrict__ rel_table) {
    __shared__ float rel[DDIM];
    const int r = blockIdx.x;
    const int k = threadIdx.x;

    const float rv_k = rel_table[r * DDIM + k];
    rel[k] = rv_k;
    __syncthreads();

    float s1 = 0.f, s2 = 0.f;
#pragma unroll 8
    for (int d = 0; d < DDIM; d++) {
        float rv = rel[d];
        s1 = fmaf(fc_W[k * DDIM + d], rv, s1);
        s2 = fmaf(fc_W[(k + DDIM) * DDIM + d], rv, s2);
    }
    // interleaved store: lane l = k>>1, parity p = k&1
    const int base = r * 4 * DDIM + (k >> 1) * 4 + (k & 1);
    g_u[base]     = s1;
    g_u[base + 2] = s2;

    // c[r] = dot(fc_b, rel[r])
    float bp = fc_b[k] * rv_k;
    bp += __shfl_xor_sync(FULLMASK, bp, 16);
    bp += __shfl_xor_sync(FULLMASK, bp, 8);
    bp += __shfl_xor_sync(FULLMASK, bp, 4);
    bp += __shfl_xor_sync(FULLMASK, bp, 2);
    bp += __shfl_xor_sync(FULLMASK, bp, 1);
    __shared__ float warp_sum[2];
    if ((k & 31) == 0) warp_sum[k >> 5] = bp;
    __syncthreads();
    if (k == 0) g_c[r] = warp_sum[0] + warp_sum[1];
}

// One warp per item row. Lane owns dims [2*lane, 2*lane+1].
__global__ void __launch_bounds__(256, 3)
gat_kernel(const int* __restrict__ item_ids,
           const int* __restrict__ item_entities,
           const int* __restrict__ item_relations,
           const float* __restrict__ item_table,
           const float* __restrict__ entity_table,
           float* __restrict__ out,
           int N) {
    const int warp = (int)((blockIdx.x * blockDim.x + threadIdx.x) >> 5);
    const int lane = threadIdx.x & 31;
    if (warp >= N) return;

    const int iid = __ldg(item_ids + warp);
    const float2 it = *(const float2*)(item_table + iid * DDIM + 2 * lane);

    // Lanes 0..15 hold the 16 neighbor (entity, relation) ids.
    int my_eid = 0, my_rid = 0;
    if (lane < MNB) {
        my_eid = __ldg(item_entities + warp * MNB + lane);
        my_rid = __ldg(item_relations + warp * MNB + lane);
    }

    // ---- Phase 1: batched gathers + per-lane partial dots ----
    float2 ent[MNB];
    float  pl[MNB];
#pragma unroll
    for (int m = 0; m < MNB; m++) {
        const int eid = __shfl_sync(FULLMASK, my_eid, m);
        ent[m] = *(const float2*)(entity_table + eid * DDIM + 2 * lane);
    }
#pragma unroll
    for (int m = 0; m < MNB; m++) {
        const int rid = __shfl_sync(FULLMASK, my_rid, m);
        const float4 u = *(const float4*)(g_u + rid * 4 * DDIM + 4 * lane);
        pl[m] = it.x * u.x + it.y * u.y + ent[m].x * u.z + ent[m].y * u.w;
    }

    // ---- Phase 2: merge-tree reduction, 16 values -> lane-distributed ----
    // After all stages, lane l holds full 32-lane sum of value ((l>>1)&15).
    const bool h16 = lane & 16, h8 = lane & 8, h4 = lane & 4, h2 = lane & 2;
#pragma unroll
    for (int i = 0; i < 8; i++) {          // offset 16: 16 -> 8
        float a = pl[i]     + __shfl_xor_sync(FULLMASK, pl[i],     16);
        float b = pl[i + 8] + __shfl_xor_sync(FULLMASK, pl[i + 8], 16);
        pl[i] = h16 ? b : a;
    }
#pragma unroll
    for (int i = 0; i < 4; i++) {          // offset 8: 8 -> 4
        float a = pl[i]     + __shfl_xor_sync(FULLMASK, pl[i],     8);
        float b = pl[i + 4] + __shfl_xor_sync(FULLMASK, pl[i + 4], 8);
        pl[i] = h8 ? b : a;
    }
#pragma unroll
    for (int i = 0; i < 2; i++) {          // offset 4: 4 -> 2
        float a = pl[i]     + __shfl_xor_sync(FULLMASK, pl[i],     4);
        float b = pl[i + 2] + __shfl_xor_sync(FULLMASK, pl[i + 2], 4);
        pl[i] = h4 ? b : a;
    }
    {                                      // offset 2: 2 -> 1
        float a = pl[0] + __shfl_xor_sync(FULLMASK, pl[0], 2);
        float b = pl[1] + __shfl_xor_sync(FULLMASK, pl[1], 2);
        pl[0] = h2 ? b : a;
    }
    float e = pl[0] + __shfl_xor_sync(FULLMASK, pl[0], 1);  // full sum

    // ---- Epilogue: one logit per lane (value idx = (lane>>1)&15) ----
    const int src = (lane >> 1) & 15;
    const int rid_v = __shfl_sync(FULLMASK, my_rid, src);
    const int eid_v = __shfl_sync(FULLMASK, my_eid, src);
    e += __ldg(g_c + rid_v);
    e = (e > 0.f) ? e : ALPHA * e;                     // leaky_relu
    e = (eid_v != NUM_ENTITIES) ? e : NEG_INF;         // padding mask

    // Softmax across the 16 distinct values: reduce over one parity class
    // (offsets 16,8,4,2) so each value is counted exactly once.
    float mx = e;
    mx = fmaxf(mx, __shfl_xor_sync(FULLMASK, mx, 16));
    mx = fmaxf(mx, __shfl_xor_sync(FULLMASK, mx, 8));
    mx = fmaxf(mx, __shfl_xor_sync(FULLMASK, mx, 4));
    mx = fmaxf(mx, __shfl_xor_sync(FULLMASK, mx, 2));
    float ex = __expf(e - mx);
    float s = ex;
    s += __shfl_xor_sync(FULLMASK, s, 16);
    s += __shfl_xor_sync(FULLMASK, s, 8);
    s += __shfl_xor_sync(FULLMASK, s, 4);
    s += __shfl_xor_sync(FULLMASK, s, 2);
    const float w = ex / s;    // lanes 2m, 2m+1 both hold weight of value m

    // ---- Weighted sum + residual ----
    float2 acc = it;
#pragma unroll
    for (int m = 0; m < MNB; m++) {
        const float wm = __shfl_sync(FULLMASK, w, m << 1);
        acc.x = fmaf(wm, ent[m].x, acc.x);
        acc.y = fmaf(wm, ent[m].y, acc.y);
    }
    *(float2*)(out + warp * DDIM + 2 * lane) = acc;
}

extern "C" void kernel_launch(void* const* d_in, const int* in_sizes, int n_in,
                              void* d_out, int out_size) {
    const int*   item_ids       = (const int*)d_in[0];
    const int*   item_entities  = (const int*)d_in[1];
    const int*   item_relations = (const int*)d_in[2];
    const float* item_table     = (const float*)d_in[3];
    const float* entity_table   = (const float*)d_in[4];
    const float* relation_table = (const float*)d_in[5];
    const float* fc_W           = (const float*)d_in[6];
    const float* fc_b           = (const float*)d_in[7];
    float* out = (float*)d_out;

    const int N = in_sizes[0];

    precompute_kernel<<<NREL, DDIM>>>(fc_W, fc_b, relation_table);

    // One warp per row: 8 rows per 256-thread block.
    const int blocks = (N + 7) / 8;
    gat_kernel<<<blocks, 256>>>(item_ids, item_entities, item_relations,
                                item_table, entity_table, out, N);
}

// round 5
// speedup vs baseline: 1.7318x; 1.1518x over previous
#include <cuda_runtime.h>
#include <cuda_fp16.h>

#define NUM_ENTITIES 200000
#define NEG_INF -9e15f
#define ALPHA 0.2f
#define DDIM 64
#define MNB 16
#define NREL 51
#define FULLMASK 0xffffffffu

// Fused per-relation projection table in fp16, lane-interleaved:
// per relation r: 32 lanes x 4 halves (8B) = 256B.
// g_uh[r*128 + lane*4 + {0,1,2,3}] = { u1[2l], u1[2l+1], u2[2l], u2[2l+1] }
// where u1[k] = sum_d fc_W[k,d]*rel[r,d], u2[k] = sum_d fc_W[k+64,d]*rel[r,d].
__device__ __align__(8) __half g_uh[NREL * 2 * DDIM];
__device__ float g_c[NREL];           // c[r] = dot(fc_b, rel[r])

// 51 blocks x 64 threads: thread k computes u1[k], u2[k] for relation r.
__global__ void precompute_kernel(const float* __restrict__ fc_W,
                                  const float* __restrict__ fc_b,
                                  const float* __restrict__ rel_table) {
    __shared__ float rel[DDIM];
    const int r = blockIdx.x;
    const int k = threadIdx.x;

    const float rv_k = rel_table[r * DDIM + k];
    rel[k] = rv_k;
    __syncthreads();

    float s1 = 0.f, s2 = 0.f;
#pragma unroll 8
    for (int d = 0; d < DDIM; d++) {
        float rv = rel[d];
        s1 = fmaf(fc_W[k * DDIM + d], rv, s1);
        s2 = fmaf(fc_W[(k + DDIM) * DDIM + d], rv, s2);
    }
    // interleaved fp16 store: lane l = k>>1, parity p = k&1
    const int base = r * 2 * DDIM + (k >> 1) * 4 + (k & 1);
    g_uh[base]     = __float2half(s1);
    g_uh[base + 2] = __float2half(s2);

    // c[r] = dot(fc_b, rel[r])  (kept fp32)
    float bp = fc_b[k] * rv_k;
    bp += __shfl_xor_sync(FULLMASK, bp, 16);
    bp += __shfl_xor_sync(FULLMASK, bp, 8);
    bp += __shfl_xor_sync(FULLMASK, bp, 4);
    bp += __shfl_xor_sync(FULLMASK, bp, 2);
    bp += __shfl_xor_sync(FULLMASK, bp, 1);
    __shared__ float warp_sum[2];
    if ((k & 31) == 0) warp_sum[k >> 5] = bp;
    __syncthreads();
    if (k == 0) g_c[r] = warp_sum[0] + warp_sum[1];
}

// One warp per item row. Lane owns dims [2*lane, 2*lane+1].
__global__ void __launch_bounds__(256, 3)
gat_kernel(const int* __restrict__ item_ids,
           const int* __restrict__ item_entities,
           const int* __restrict__ item_relations,
           const float* __restrict__ item_table,
           const float* __restrict__ entity_table,
           float* __restrict__ out,
           int N) {
    const int warp = (int)((blockIdx.x * blockDim.x + threadIdx.x) >> 5);
    const int lane = threadIdx.x & 31;
    if (warp >= N) return;

    const int iid = __ldg(item_ids + warp);
    const float2 it = *(const float2*)(item_table + iid * DDIM + 2 * lane);

    // Lanes 0..15 hold the 16 neighbor (entity, relation) ids.
    int my_eid = 0, my_rid = 0;
    if (lane < MNB) {
        my_eid = __ldg(item_entities + warp * MNB + lane);
        my_rid = __ldg(item_relations + warp * MNB + lane);
    }

    // ---- Phase 1: batched gathers + per-lane partial dots ----
    float2 ent[MNB];
    float  pl[MNB];
#pragma unroll
    for (int m = 0; m < MNB; m++) {
        const int eid = __shfl_sync(FULLMASK, my_eid, m);
        ent[m] = *(const float2*)(entity_table + eid * DDIM + 2 * lane);
    }
#pragma unroll
    for (int m = 0; m < MNB; m++) {
        const int rid = __shfl_sync(FULLMASK, my_rid, m);
        // 8-byte fp16 load: {u1 pair, u2 pair} for this lane's dims.
        const __half2* up = (const __half2*)(g_uh + rid * 2 * DDIM + 4 * lane);
        const float2 u1 = __half22float2(up[0]);
        const float2 u2 = __half22float2(up[1]);
        pl[m] = it.x * u1.x + it.y * u1.y + ent[m].x * u2.x + ent[m].y * u2.y;
    }

    // ---- Phase 2: merge-tree reduction, 16 values -> lane-distributed ----
    // After all stages, lane l holds full 32-lane sum of value ((l>>1)&15).
    const bool h16 = lane & 16, h8 = lane & 8, h4 = lane & 4, h2 = lane & 2;
#pragma unroll
    for (int i = 0; i < 8; i++) {          // offset 16: 16 -> 8
        float a = pl[i]     + __shfl_xor_sync(FULLMASK, pl[i],     16);
        float b = pl[i + 8] + __shfl_xor_sync(FULLMASK, pl[i + 8], 16);
        pl[i] = h16 ? b : a;
    }
#pragma unroll
    for (int i = 0; i < 4; i++) {          // offset 8: 8 -> 4
        float a = pl[i]     + __shfl_xor_sync(FULLMASK, pl[i],     8);
        float b = pl[i + 4] + __shfl_xor_sync(FULLMASK, pl[i + 4], 8);
        pl[i] = h8 ? b : a;
    }
#pragma unroll
    for (int i = 0; i < 2; i++) {          // offset 4: 4 -> 2
        float a = pl[i]     + __shfl_xor_sync(FULLMASK, pl[i],     4);
        float b = pl[i + 2] + __shfl_xor_sync(FULLMASK, pl[i + 2], 4);
        pl[i] = h4 ? b : a;
    }
    {                                      // offset 2: 2 -> 1
        float a = pl[0] + __shfl_xor_sync(FULLMASK, pl[0], 2);
        float b = pl[1] + __shfl_xor_sync(FULLMASK, pl[1], 2);
        pl[0] = h2 ? b : a;
    }
    float e = pl[0] + __shfl_xor_sync(FULLMASK, pl[0], 1);  // full sum

    // ---- Epilogue: one logit per lane (value idx = (lane>>1)&15) ----
    const int src = (lane >> 1) & 15;
    const int rid_v = __shfl_sync(FULLMASK, my_rid, src);
    const int eid_v = __shfl_sync(FULLMASK, my_eid, src);
    e += __ldg(g_c + rid_v);
    e = (e > 0.f) ? e : ALPHA * e;                     // leaky_relu
    e = (eid_v != NUM_ENTITIES) ? e : NEG_INF;         // padding mask

    // Softmax across the 16 distinct values: reduce over one parity class
    // (offsets 16,8,4,2) so each value is counted exactly once.
    float mx = e;
    mx = fmaxf(mx, __shfl_xor_sync(FULLMASK, mx, 16));
    mx = fmaxf(mx, __shfl_xor_sync(FULLMASK, mx, 8));
    mx = fmaxf(mx, __shfl_xor_sync(FULLMASK, mx, 4));
    mx = fmaxf(mx, __shfl_xor_sync(FULLMASK, mx, 2));
    float ex = __expf(e - mx);
    float s = ex;
    s += __shfl_xor_sync(FULLMASK, s, 16);
    s += __shfl_xor_sync(FULLMASK, s, 8);
    s += __shfl_xor_sync(FULLMASK, s, 4);
    s += __shfl_xor_sync(FULLMASK, s, 2);
    const float w = __fdividef(ex, s);  // lanes 2m,2m+1 hold weight of value m

    // ---- Weighted sum + residual ----
    float2 acc = it;
#pragma unroll
    for (int m = 0; m < MNB; m++) {
        const float wm = __shfl_sync(FULLMASK, w, m << 1);
        acc.x = fmaf(wm, ent[m].x, acc.x);
        acc.y = fmaf(wm, ent[m].y, acc.y);
    }
    *(float2*)(out + warp * DDIM + 2 * lane) = acc;
}

extern "C" void kernel_launch(void* const* d_in, const int* in_sizes, int n_in,
                              void* d_out, int out_size) {
    const int*   item_ids       = (const int*)d_in[0];
    const int*   item_entities  = (const int*)d_in[1];
    const int*   item_relations = (const int*)d_in[2];
    const float* item_table     = (const float*)d_in[3];
    const float* entity_table   = (const float*)d_in[4];
    const float* relation_table = (const float*)d_in[5];
    const float* fc_W           = (const float*)d_in[6];
    const float* fc_b           = (const float*)d_in[7];
    float* out = (float*)d_out;

    const int N = in_sizes[0];

    precompute_kernel<<<NREL, DDIM>>>(fc_W, fc_b, relation_table);

    // One warp per row: 8 rows per 256-thread block.
    const int blocks = (N + 7) / 8;
    gat_kernel<<<blocks, 256>>>(item_ids, item_entities, item_relations,
                                item_table, entity_table, out, N);
}